// round 2
// baseline (speedup 1.0000x reference)
#include <cuda_runtime.h>

// MonarchConv: y = ifft(fft(u,2N) * fft(k,2N))[:L].real + u*D
// B=16, H=512, L=1024, NFFT=2048. The reference's block-FFT with broadcast DFT
// matrices is exactly a standard length-2048 DFT, so we implement FFT conv
// directly and ignore the mat_* inputs.

#define NFFT   2048
#define LOG2N  11
#define LSEQ   1024
#define NH     512
#define NB     16
#define NROWS  (NB * NH)
#define TPB    512

// k_f (bit-reversed DIF order), scaled by 1/NFFT. 512*2048*8B = 8 MB.
__device__ float2 g_kf[NH * NFFT];
// Twiddle table: g_tw[j] = exp(-2*pi*i*j/NFFT), j = 0..NFFT/2-1. 8 KB.
__device__ float2 g_tw[NFFT / 2];

__global__ void init_tw_kernel() {
    int j = blockIdx.x * blockDim.x + threadIdx.x;
    if (j < NFFT / 2) {
        float ang = -6.283185307179586f * (float)j / (float)NFFT;
        g_tw[j] = make_float2(cosf(ang), sinf(ang));
    }
}

__device__ __forceinline__ float2 cmul(float2 a, float2 b) {
    return make_float2(fmaf(a.x, b.x, -a.y * b.y),
                       fmaf(a.x, b.y,  a.y * b.x));
}

// Forward DIF FFT: natural order in -> bit-reversed order out.
__device__ __forceinline__ void fft_fwd(float2* sm, int tid) {
    #pragma unroll
    for (int s = LOG2N; s >= 1; --s) {
        int half = 1 << (s - 1);
        #pragma unroll
        for (int kk = 0; kk < NFFT / 2; kk += TPB) {
            int k = kk + tid;
            int j = k & (half - 1);
            int base = ((k >> (s - 1)) << s) + j;
            float2 a = sm[base];
            float2 b = sm[base + half];
            float2 w = g_tw[j << (LOG2N - s)];
            sm[base] = make_float2(a.x + b.x, a.y + b.y);
            float2 d = make_float2(a.x - b.x, a.y - b.y);
            sm[base + half] = cmul(d, w);
        }
        __syncthreads();
    }
}

// Inverse DIT FFT: bit-reversed order in -> natural order out (unscaled).
__device__ __forceinline__ void fft_inv(float2* sm, int tid) {
    #pragma unroll
    for (int s = 1; s <= LOG2N; ++s) {
        int half = 1 << (s - 1);
        #pragma unroll
        for (int kk = 0; kk < NFFT / 2; kk += TPB) {
            int k = kk + tid;
            int j = k & (half - 1);
            int base = ((k >> (s - 1)) << s) + j;
            float2 w = g_tw[j << (LOG2N - s)];
            w.y = -w.y;  // conjugate for inverse
            float2 t = cmul(sm[base + half], w);
            float2 a = sm[base];
            sm[base]        = make_float2(a.x + t.x, a.y + t.y);
            sm[base + half] = make_float2(a.x - t.x, a.y - t.y);
        }
        __syncthreads();
    }
}

__global__ __launch_bounds__(TPB) void kf_kernel(const float* __restrict__ k) {
    __shared__ float2 sm[NFFT];
    int h = blockIdx.x;
    int tid = threadIdx.x;
    for (int i = tid; i < LSEQ; i += TPB) {
        sm[i]        = make_float2(k[h * LSEQ + i], 0.f);
        sm[i + LSEQ] = make_float2(0.f, 0.f);
    }
    __syncthreads();
    fft_fwd(sm, tid);
    const float scale = 1.0f / (float)NFFT;  // fold 1/N of the ifft into k_f
    for (int i = tid; i < NFFT; i += TPB) {
        float2 v = sm[i];
        g_kf[h * NFFT + i] = make_float2(v.x * scale, v.y * scale);
    }
}

__global__ __launch_bounds__(TPB) void conv_kernel(const float* __restrict__ u,
                                                   const float* __restrict__ D,
                                                   float* __restrict__ y) {
    __shared__ float2 sm[NFFT];
    __shared__ float  su[LSEQ];
    int row = blockIdx.x;          // row = b*NH + h
    int h = row & (NH - 1);
    int tid = threadIdx.x;
    const float* up = u + (size_t)row * LSEQ;

    for (int i = tid; i < LSEQ; i += TPB) {
        float v = up[i];
        su[i] = v;
        sm[i]        = make_float2(v, 0.f);
        sm[i + LSEQ] = make_float2(0.f, 0.f);
    }
    __syncthreads();

    fft_fwd(sm, tid);

    const float2* __restrict__ kf = g_kf + (size_t)h * NFFT;
    for (int i = tid; i < NFFT; i += TPB) {
        sm[i] = cmul(sm[i], kf[i]);
    }
    __syncthreads();

    fft_inv(sm, tid);

    float d = D[h];
    float* yp = y + (size_t)row * LSEQ;
    for (int i = tid; i < LSEQ; i += TPB) {
        yp[i] = fmaf(su[i], d, sm[i].x);
    }
}

extern "C" void kernel_launch(void* const* d_in, const int* in_sizes, int n_in,
                              void* d_out, int out_size) {
    const float* u = (const float*)d_in[0];   // (B, H, L)
    const float* k = (const float*)d_in[1];   // (H, L)
    const float* D = (const float*)d_in[2];   // (H,)
    float* y = (float*)d_out;                 // (B, H, L)

    init_tw_kernel<<<(NFFT / 2 + 255) / 256, 256>>>();
    kf_kernel<<<NH, TPB>>>(k);
    conv_kernel<<<NROWS, TPB>>>(u, D, y);
}

// round 6
// speedup vs baseline: 3.0227x; 3.0227x over previous
#include <cuda_runtime.h>

// MonarchConv: y = ifft(fft(u,2048) * fft(k,2048))[:1024].real + u*D
// Radix 16*16*8 register FFT, 128 thr * 16 float2/thread, batch-paired
// (two real rows packed into one complex FFT).

#define NFFT   2048
#define LSEQ   1024
#define NH     512
#define NB     16
#define TPB    128

// pad +2 float2 per 32 logical elements
#define PHYS(i) ((i) + ((((i) >> 5)) << 1))

__device__ float2 g_kf[NH * NFFT];   // scrambled-order spectrum of k, * 1/2048
__device__ float2 g_tw[1024];        // exp(-2*pi*i*j/2048), j=0..1023

__global__ void init_tw_kernel() {
    int j = blockIdx.x * blockDim.x + threadIdx.x;
    if (j < 1024) {
        double ang = -6.283185307179586476925287 * (double)j / 2048.0;
        g_tw[j] = make_float2((float)cos(ang), (float)sin(ang));
    }
}

__device__ __forceinline__ float2 cadd(float2 a, float2 b) { return make_float2(a.x + b.x, a.y + b.y); }
__device__ __forceinline__ float2 csub(float2 a, float2 b) { return make_float2(a.x - b.x, a.y - b.y); }
__device__ __forceinline__ float2 cmul(float2 a, float2 b) {
    return make_float2(fmaf(a.x, b.x, -a.y * b.y), fmaf(a.x, b.y, a.y * b.x));
}

// twiddle exp(-2*pi*i*idx/2048), 0 <= idx < 2048
__device__ __forceinline__ float2 twd(int idx) {
    float2 w = g_tw[idx & 1023];
    if (idx & 1024) { w.x = -w.x; w.y = -w.y; }
    return w;
}

// DFT4: o_t = sum_s x_s * exp(-+2*pi*i*s*t/4).  INV=0 fwd, INV=1 inv (unscaled).
template<int INV>
__device__ __forceinline__ void dft4(float2 a, float2 b, float2 c, float2 d,
                                     float2& o0, float2& o1, float2& o2, float2& o3) {
    float2 t0 = cadd(a, c), t1 = csub(a, c);
    float2 t2 = cadd(b, d), t3 = csub(b, d);
    o0 = cadd(t0, t2);
    o2 = csub(t0, t2);
    float2 r = INV ? make_float2(-t3.y, t3.x) : make_float2(t3.y, -t3.x); // +-i * t3
    o1 = cadd(t1, r);
    o3 = csub(t1, r);
}

template<int INV>
__device__ __forceinline__ float2 w16c(int k) { // exp(-2*pi*i*k/16), conj for INV
    const float C1 = 0.9238795325112867f, S1 = 0.3826834323650898f, C2 = 0.7071067811865476f;
    float2 w = make_float2(1.f, 0.f);
    if (k == 1) w = make_float2(C1, -S1);
    if (k == 2) w = make_float2(C2, -C2);
    if (k == 3) w = make_float2(S1, -C1);
    if (k == 4) w = make_float2(0.f, -1.f);
    if (k == 6) w = make_float2(-C2, -C2);
    if (k == 9) w = make_float2(-C1, S1);
    if (INV) w.y = -w.y;
    return w;
}

// 16-point DFT in place, natural in/out. y_t = sum_s x_s exp(-+2*pi*i*s*t/16).
template<int INV>
__device__ __forceinline__ void dft16(float2* x) {
    float2 A[16];  // A[q*4+u]
    dft4<INV>(x[0], x[4], x[8],  x[12], A[0], A[4], A[8],  A[12]);  // u=0
    dft4<INV>(x[1], x[5], x[9],  x[13], A[1], A[5], A[9],  A[13]);  // u=1
    dft4<INV>(x[2], x[6], x[10], x[14], A[2], A[6], A[10], A[14]);  // u=2
    dft4<INV>(x[3], x[7], x[11], x[15], A[3], A[7], A[11], A[15]);  // u=3
    // A[q*4+u] *= w16^(u*q)
    A[4 + 1]  = cmul(A[4 + 1],  w16c<INV>(1));
    A[4 + 2]  = cmul(A[4 + 2],  w16c<INV>(2));
    A[4 + 3]  = cmul(A[4 + 3],  w16c<INV>(3));
    A[8 + 1]  = cmul(A[8 + 1],  w16c<INV>(2));
    A[8 + 2]  = cmul(A[8 + 2],  w16c<INV>(4));
    A[8 + 3]  = cmul(A[8 + 3],  w16c<INV>(6));
    A[12 + 1] = cmul(A[12 + 1], w16c<INV>(3));
    A[12 + 2] = cmul(A[12 + 2], w16c<INV>(6));
    A[12 + 3] = cmul(A[12 + 3], w16c<INV>(9));
    dft4<INV>(A[0],  A[1],  A[2],  A[3],  x[0], x[4], x[8],  x[12]);
    dft4<INV>(A[4],  A[5],  A[6],  A[7],  x[1], x[5], x[9],  x[13]);
    dft4<INV>(A[8],  A[9],  A[10], A[11], x[2], x[6], x[10], x[14]);
    dft4<INV>(A[12], A[13], A[14], A[15], x[3], x[7], x[11], x[15]);
}

// 8-point DFT in place.
template<int INV>
__device__ __forceinline__ void dft8(float2* x) {
    float2 A0, A1, A2, A3, B0, B1, B2, B3;
    dft4<INV>(x[0], x[2], x[4], x[6], A0, A1, A2, A3);
    dft4<INV>(x[1], x[3], x[5], x[7], B0, B1, B2, B3);
    const float C2 = 0.7071067811865476f;
    float2 w1 = INV ? make_float2(C2, C2) : make_float2(C2, -C2);
    float2 w3 = INV ? make_float2(-C2, C2) : make_float2(-C2, -C2);
    B1 = cmul(B1, w1);
    B2 = INV ? make_float2(-B2.y, B2.x) : make_float2(B2.y, -B2.x);
    B3 = cmul(B3, w3);
    x[0] = cadd(A0, B0); x[4] = csub(A0, B0);
    x[1] = cadd(A1, B1); x[5] = csub(A1, B1);
    x[2] = cadd(A2, B2); x[6] = csub(A2, B2);
    x[3] = cadd(A3, B3); x[7] = csub(A3, B3);
}

// ---- forward FFT body (shared by kf and conv). Data ends scrambled:
// addr(k) = (k&15)*128 + ((k>>4)&15)*8 + (k>>8)

__device__ __forceinline__ void fwd_pass0_store(float2* x, float2* sm, int tid) {
    dft16<0>(x);
    #pragma unroll
    for (int t = 1; t < 16; t++) x[t] = cmul(x[t], twd(tid * t));
    #pragma unroll
    for (int t = 0; t < 16; t++) sm[PHYS(tid + 128 * t)] = x[t];
}

__device__ __forceinline__ void fwd_pass1(float2* x, float2* sm, int tid) {
    int base = (tid >> 3) * 128 + (tid & 7);
    int j = tid & 7;
    #pragma unroll
    for (int t = 0; t < 16; t++) x[t] = sm[PHYS(base + 8 * t)];
    dft16<0>(x);
    #pragma unroll
    for (int t = 1; t < 16; t++) x[t] = cmul(x[t], twd(16 * j * t));
    #pragma unroll
    for (int t = 0; t < 16; t++) sm[PHYS(base + 8 * t)] = x[t];
}

__device__ __forceinline__ void fwd_pass2_load(float2* x, const float2* sm, int tid) {
    int base = tid * 16;
    #pragma unroll
    for (int s = 0; s < 16; s++) x[s] = sm[PHYS(base + s)];
    dft8<0>(x);
    dft8<0>(x + 8);
}

__global__ __launch_bounds__(TPB) void kf_kernel(const float* __restrict__ kin) {
    __shared__ float2 sm[2176];
    int tid = threadIdx.x;
    int h = blockIdx.x;
    const float* kr = kin + (size_t)h * LSEQ;
    float2 x[16];
    #pragma unroll
    for (int t = 0; t < 8; t++) x[t] = make_float2(kr[tid + 128 * t], 0.f);
    #pragma unroll
    for (int t = 8; t < 16; t++) x[t] = make_float2(0.f, 0.f);
    fwd_pass0_store(x, sm, tid);
    __syncthreads();
    fwd_pass1(x, sm, tid);
    __syncthreads();
    fwd_pass2_load(x, sm, tid);
    const float sc = 1.0f / (float)NFFT;
    float2* out = g_kf + (size_t)h * NFFT + tid * 16;
    #pragma unroll
    for (int s = 0; s < 16; s++) out[s] = make_float2(x[s].x * sc, x[s].y * sc);
}

__global__ __launch_bounds__(TPB) void conv_kernel(const float* __restrict__ u,
                                                   const float* __restrict__ D,
                                                   float* __restrict__ y) {
    __shared__ float2 sm[2176];
    const int tid = threadIdx.x;
    const int h = blockIdx.x & (NH - 1);
    const int p = blockIdx.x >> 9;
    const size_t off0 = ((size_t)(2 * p) * NH + h) * LSEQ;
    const float* u0 = u + off0;
    const float* u1 = u0 + (size_t)NH * LSEQ;
    float2 x[16];

    // forward: z = u0 + i*u1, zero-padded
    #pragma unroll
    for (int t = 0; t < 8; t++)
        x[t] = make_float2(u0[tid + 128 * t], u1[tid + 128 * t]);
    #pragma unroll
    for (int t = 8; t < 16; t++) x[t] = make_float2(0.f, 0.f);
    fwd_pass0_store(x, sm, tid);
    __syncthreads();
    fwd_pass1(x, sm, tid);
    __syncthreads();
    fwd_pass2_load(x, sm, tid);
    {
        int base = tid * 16;
        #pragma unroll
        for (int s = 0; s < 16; s++) sm[PHYS(base + s)] = x[s];
    }
    __syncthreads();

    // pairing: Hermitian split, multiply by kf, repack
    {
        const float2* kf = g_kf + (size_t)h * NFFT;
        #pragma unroll
        for (int it = 0; it < 8; it++) {
            int k = tid + 128 * it;
            if (k == 0) {
                float2 Z0 = sm[PHYS(0)];
                float f0 = kf[0].x;
                sm[PHYS(0)] = make_float2(Z0.x * f0, Z0.y * f0);
                float2 Zh = sm[PHYS(4)];   // addr(1024) = 4
                float fh = kf[4].x;
                sm[PHYS(4)] = make_float2(Zh.x * fh, Zh.y * fh);
            } else {
                int m = NFFT - k;
                int ak = ((k & 15) << 7) | (((k >> 4) & 15) << 3) | (k >> 8);
                int am = ((m & 15) << 7) | (((m >> 4) & 15) << 3) | (m >> 8);
                float2 Zk = sm[PHYS(ak)];
                float2 Zm = sm[PHYS(am)];
                float2 kfk = kf[ak];
                float2 S  = make_float2(0.5f * (Zk.x + Zm.x), 0.5f * (Zk.y - Zm.y)); // U0[k]
                float2 T  = make_float2(0.5f * (Zk.x - Zm.x), 0.5f * (Zk.y + Zm.y));
                float2 U1 = make_float2(T.y, -T.x);                                  // -i*T
                float2 Y0 = cmul(S, kfk);
                float2 Y1 = cmul(U1, kfk);
                sm[PHYS(ak)] = make_float2(Y0.x - Y1.y, Y0.y + Y1.x);        // W[k] = Y0 + i*Y1
                sm[PHYS(am)] = make_float2(Y0.x + Y1.y, Y1.x - Y0.y);        // W[m] = conj(Y0 - i*Y1)
            }
        }
    }
    __syncthreads();

    // inverse pass2'
    {
        int base = tid * 16;
        #pragma unroll
        for (int s = 0; s < 16; s++) x[s] = sm[PHYS(base + s)];
        dft8<1>(x);
        dft8<1>(x + 8);
        #pragma unroll
        for (int s = 0; s < 16; s++) sm[PHYS(base + s)] = x[s];
    }
    __syncthreads();

    // inverse pass1'
    {
        int base = (tid >> 3) * 128 + (tid & 7);
        int j = tid & 7;
        #pragma unroll
        for (int t = 0; t < 16; t++) x[t] = sm[PHYS(base + 8 * t)];
        #pragma unroll
        for (int t = 1; t < 16; t++) {
            float2 w = twd(16 * j * t); w.y = -w.y;
            x[t] = cmul(x[t], w);
        }
        dft16<1>(x);
        #pragma unroll
        for (int t = 0; t < 16; t++) sm[PHYS(base + 8 * t)] = x[t];
    }
    __syncthreads();

    // inverse pass0' + epilogue (only s=0..7 are within the output length)
    {
        #pragma unroll
        for (int t = 0; t < 16; t++) x[t] = sm[PHYS(tid + 128 * t)];
        #pragma unroll
        for (int t = 1; t < 16; t++) {
            float2 w = twd(tid * t); w.y = -w.y;
            x[t] = cmul(x[t], w);
        }
        dft16<1>(x);
        float d = D[h];
        float* y0 = y + off0;
        float* y1 = y0 + (size_t)NH * LSEQ;
        #pragma unroll
        for (int s = 0; s < 8; s++) {
            int i = tid + 128 * s;
            y0[i] = fmaf(u0[i], d, x[s].x);
            y1[i] = fmaf(u1[i], d, x[s].y);
        }
    }
}

extern "C" void kernel_launch(void* const* d_in, const int* in_sizes, int n_in,
                              void* d_out, int out_size) {
    const float* u = (const float*)d_in[0];   // (B, H, L)
    const float* k = (const float*)d_in[1];   // (H, L)
    const float* D = (const float*)d_in[2];   // (H,)
    float* y = (float*)d_out;                 // (B, H, L)

    init_tw_kernel<<<4, 256>>>();
    kf_kernel<<<NH, TPB>>>(k);
    conv_kernel<<<(NB / 2) * NH, TPB>>>(u, D, y);
}